// round 14
// baseline (speedup 1.0000x reference)
#include <cuda_runtime.h>
#include <cstdint>

// Problem constants
#define BATCH 2
#define SEQ   2048
#define HID   2048
#define NHEAD 16
#define HDIM  128
#define MROWS (BATCH * SEQ)   // 4096
#define K3    (3 * HID)       // 6144

// Scratch (allocation-free rule: __device__ globals)
__device__ float g_qkv[(size_t)MROWS * K3];   // [4096, 6144]
__device__ float g_ctx[(size_t)MROWS * HID];  // [4096, 2048]
__device__ float g_x  [(size_t)MROWS * HID];  // tf32-truncated x
__device__ float g_wq [(size_t)HID * K3];     // tf32-truncated w_qkv TRANSPOSED [6144][2048]
__device__ float g_wo [(size_t)HID * HID];    // tf32-truncated w_out TRANSPOSED [2048][2048]

__device__ __forceinline__ unsigned f2tf(float x) {
    unsigned u;
    asm("cvt.rna.tf32.f32 %0, %1;" : "=r"(u) : "f"(x));
    return u;
}

__device__ __forceinline__ void mma_tf32(float* d, const unsigned* a, const unsigned* b) {
    asm volatile(
        "mma.sync.aligned.m16n8k8.row.col.f32.tf32.tf32.f32 "
        "{%0,%1,%2,%3},{%4,%5,%6,%7},{%8,%9},{%0,%1,%2,%3};"
        : "+f"(d[0]), "+f"(d[1]), "+f"(d[2]), "+f"(d[3])
        : "r"(a[0]), "r"(a[1]), "r"(a[2]), "r"(a[3]), "r"(b[0]), "r"(b[1]));
}

__device__ __forceinline__ void cp16(unsigned dst, const void* src) {
    asm volatile("cp.async.cg.shared.global [%0], [%1], 16;\n" :: "r"(dst), "l"(src));
}

__device__ __forceinline__ void ldsm_x4(unsigned& r0, unsigned& r1, unsigned& r2,
                                        unsigned& r3, unsigned addr) {
    asm volatile("ldmatrix.sync.aligned.m8n8.x4.shared.b16 {%0,%1,%2,%3}, [%4];"
                 : "=r"(r0), "=r"(r1), "=r"(r2), "=r"(r3) : "r"(addr));
}

// ===========================================================================
// Preprocessing: tf32 truncating copy / truncating transpose
// ===========================================================================
__global__ void trunc_copy_kernel(const float4* __restrict__ src,
                                  float4* __restrict__ dst, int n4) {
    int i = blockIdx.x * blockDim.x + threadIdx.x;
    if (i < n4) {
        float4 v = src[i];
        v.x = __uint_as_float(f2tf(v.x));
        v.y = __uint_as_float(f2tf(v.y));
        v.z = __uint_as_float(f2tf(v.z));
        v.w = __uint_as_float(f2tf(v.w));
        dst[i] = v;
    }
}

// src[R][C] -> dst[C][R], truncated to tf32
__global__ void trunc_transpose_kernel(const float* __restrict__ src,
                                       float* __restrict__ dst, int R, int C) {
    __shared__ float t[32][33];
    const int c0 = blockIdx.x * 32, r0 = blockIdx.y * 32;
    const int tx = threadIdx.x, ty = threadIdx.y;
#pragma unroll
    for (int j = 0; j < 32; j += 8)
        t[ty + j][tx] = src[(size_t)(r0 + ty + j) * C + c0 + tx];
    __syncthreads();
#pragma unroll
    for (int j = 0; j < 32; j += 8)
        dst[(size_t)(c0 + ty + j) * R + r0 + tx] = __uint_as_float(f2tf(t[tx][ty + j]));
}

// ===========================================================================
// tf32 mma.sync GEMM: C[M,N] = A[M,K] @ Bt[N,K]^T + bias
// Block 128x128, BK=32, 256 threads (8 warps 2m x 4n, warp tile 64x32).
// A smem [m][32k] and B smem [n][32k], 16B-granule XOR swizzle.
// Fragments loaded via ldmatrix.x4 (canonical tf32 layout: k = c, c+4).
// 3-stage cp.async pipeline, ONE __syncthreads per iter, zero mainloop CVT.
// ===========================================================================
#define GA_W 4096                    // A stage words (128*32)
#define GSTAGE_W 8192                // A + B stage words (32KB)
#define G_SMEM_BYTES (3 * GSTAGE_W * 4)   // 98304

template <bool TRUNC_OUT>
__global__ __launch_bounds__(256, 2)
void sgemm_tf32_kernel(const float* __restrict__ A, const float* __restrict__ Bt,
                       const float* __restrict__ bias, float* __restrict__ C,
                       int N, int K) {
    extern __shared__ float sm[];
    const int tid = threadIdx.x;
    const int lane = tid & 31;
    const int warp = tid >> 5;
    const int wm = warp & 1;        // 0..1  (64-row half)
    const int wn = warp >> 1;       // 0..3  (32-col quarter)
    const int bm = blockIdx.y * 128;
    const int bn = blockIdx.x * 128;

    const int g = lane >> 2;        // 0..7
    const int c = lane & 3;         // 0..3
    const int lj = lane >> 3;       // ldmatrix lane-group 0..3
    const int lr = lane & 7;        // row within group

    unsigned smu;
    { unsigned long long p = __cvta_generic_to_shared(sm); smu = (unsigned)p; }

    // copy mapping: A 4 chunks, B 4 chunks of 16B per stage
    unsigned aDst[4]; const float* aSrc[4];
    unsigned bDst[4]; const float* bSrc[4];
#pragma unroll
    for (int r = 0; r < 4; r++) {
        int a = tid + 256 * r;
        int row = a >> 3, cc = a & 7;
        unsigned sw = (unsigned)(row * 32 + ((cc * 4) ^ ((row & 3) * 8))) * 4;
        aDst[r] = smu + sw;
        bDst[r] = smu + (unsigned)(GA_W * 4) + sw;
        aSrc[r] = A  + (size_t)(bm + row) * K + cc * 4;
        bSrc[r] = Bt + (size_t)(bn + row) * K + cc * 4;
    }

    // ldmatrix per-lane bases
    // A matrices for mt: mat j -> row base + (j&1)*8 + lr, k-chunk 2s + (j>>1)
    unsigned aLBase[4], aLSwz[4];
    const int cjA = lj >> 1;
#pragma unroll
    for (int mt = 0; mt < 4; mt++) {
        int m = wm * 64 + mt * 16 + (lj & 1) * 8 + lr;
        aLBase[mt] = (unsigned)(m * 128);
        aLSwz[mt] = (unsigned)((m & 3) * 32);
    }
    // B matrices for pair p (nt=2p,2p+1): mat j -> n row + (j>>1)*8, chunk 2s + (j&1)
    unsigned bLBase[2], bLSwz[2];
    const int cjB = lj & 1;
#pragma unroll
    for (int p = 0; p < 2; p++) {
        int n = wn * 32 + p * 16 + (lj >> 1) * 8 + lr;
        bLBase[p] = (unsigned)(GA_W * 4 + n * 128);
        bLSwz[p] = (unsigned)((n & 3) * 32);
    }

    float acc[4][4][4];
#pragma unroll
    for (int mt = 0; mt < 4; mt++)
#pragma unroll
        for (int nt = 0; nt < 4; nt++)
#pragma unroll
            for (int r = 0; r < 4; r++) acc[mt][nt][r] = 0.f;

    const int T = K / 32;

    auto issue = [&](int i) {
        const unsigned so = (unsigned)((i % 3) * GSTAGE_W) * 4;
        const int k0 = i * 32;
#pragma unroll
        for (int r = 0; r < 4; r++) {
            cp16(aDst[r] + so, aSrc[r] + k0);
            cp16(bDst[r] + so, bSrc[r] + k0);
        }
    };

    issue(0);
    asm volatile("cp.async.commit_group;\n");
    issue(1);
    asm volatile("cp.async.commit_group;\n");

    for (int i = 0; i < T; i++) {
        asm volatile("cp.async.wait_group 1;\n");
        __syncthreads();

        if (i + 2 < T) issue(i + 2);
        asm volatile("cp.async.commit_group;\n");

        const unsigned stage = smu + (unsigned)((i % 3) * GSTAGE_W) * 4;

#pragma unroll
        for (int s = 0; s < 4; s++) {
            const unsigned offA = (unsigned)((2 * s + cjA) << 4);
            const unsigned offB = (unsigned)((2 * s + cjB) << 4);
            unsigned av[4][4];
#pragma unroll
            for (int mt = 0; mt < 4; mt++)
                ldsm_x4(av[mt][0], av[mt][1], av[mt][2], av[mt][3],
                        stage + aLBase[mt] + (offA ^ aLSwz[mt]));
            unsigned bv[2][4];
#pragma unroll
            for (int p = 0; p < 2; p++)
                ldsm_x4(bv[p][0], bv[p][1], bv[p][2], bv[p][3],
                        stage + bLBase[p] + (offB ^ bLSwz[p]));
#pragma unroll
            for (int mt = 0; mt < 4; mt++)
#pragma unroll
                for (int nt = 0; nt < 4; nt++)
                    mma_tf32(acc[mt][nt], av[mt], &bv[nt >> 1][(nt & 1) * 2]);
        }
    }

    // epilogue: add bias, write float2 pairs (accumulator cols 2c, 2c+1)
#pragma unroll
    for (int mt = 0; mt < 4; mt++) {
        const int row = bm + wm * 64 + mt * 16 + g;
#pragma unroll
        for (int nt = 0; nt < 4; nt++) {
            const int col = bn + wn * 32 + nt * 8 + 2 * c;
            const float b0 = __ldg(&bias[col]);
            const float b1 = __ldg(&bias[col + 1]);
            float v00 = acc[mt][nt][0] + b0, v01 = acc[mt][nt][1] + b1;
            float v10 = acc[mt][nt][2] + b0, v11 = acc[mt][nt][3] + b1;
            if (TRUNC_OUT) {
                v00 = __uint_as_float(f2tf(v00));
                v01 = __uint_as_float(f2tf(v01));
                v10 = __uint_as_float(f2tf(v10));
                v11 = __uint_as_float(f2tf(v11));
            }
            float2 o0 = {v00, v01}, o1 = {v10, v11};
            *(float2*)(C + (size_t)row * N + col) = o0;
            *(float2*)(C + (size_t)(row + 8) * N + col) = o1;
        }
    }
}

// ===========================================================================
// Tensor-core causal flash attention (tf32 mma.sync) — unchanged (permuted
// k-layout; S fragments reused as P A-operands)
// ===========================================================================
#define K_STW 8192
#define V_STW 8448
#define V_BASE_W 16384
#define AT_SMEM_BYTES ((V_BASE_W + 2 * V_STW) * 4)   // 133120

__global__ __launch_bounds__(256, 1)
void flash_attn_tc_kernel(const float* __restrict__ qkv, float* __restrict__ ctx) {
    extern __shared__ float sm[];
    const int tid = threadIdx.x;
    const int lane = tid & 31;
    const int wid = tid >> 5;
    const int g = lane >> 2;
    const int c = lane & 3;
    const int qt = 15 - blockIdx.x;
    const int h = blockIdx.y;
    const int b = blockIdx.z;
    const int q0 = qt * 128;
    const float scale = 0.08838834764831845f;

    const float* base = qkv + ((size_t)b * SEQ) * K3 + (size_t)h * (3 * HDIM);

    unsigned smu;
    { unsigned long long p = __cvta_generic_to_shared(sm); smu = (unsigned)p; }

    const int ntiles = 2 * qt + 2;

    auto issue_tile = [&](int j, int st) {
        const float* kvb = base + (size_t)(j * 64) * K3;
#pragma unroll
        for (int r = 0; r < 8; r++) {
            int chunk = tid + 256 * r;
            int row = chunk >> 5;
            int cw = (chunk & 31) * 4;
            const float* src = kvb + (size_t)row * K3 + cw;
            unsigned kd = smu + (unsigned)(st * K_STW + row * 128 + (cw ^ ((row & 3) * 8))) * 4;
            unsigned vd = smu + (unsigned)(V_BASE_W + st * V_STW + row * 132 + cw) * 4;
            cp16(kd, src + HDIM);
            cp16(vd, src + 2 * HDIM);
        }
    };

    issue_tile(0, 0);
    asm volatile("cp.async.commit_group;\n");

    unsigned qf[16][4];
    {
        const float* qrow = base + (size_t)(q0 + wid * 16 + g) * K3;
        const float* qrow8 = qrow + 8 * (size_t)K3;
#pragma unroll
        for (int s = 0; s < 16; s++) {
            float2 f0 = *(const float2*)(qrow + 8 * s + 2 * c);
            float2 f1 = *(const float2*)(qrow8 + 8 * s + 2 * c);
            qf[s][0] = __float_as_uint(f0.x);
            qf[s][2] = __float_as_uint(f0.y);
            qf[s][1] = __float_as_uint(f1.x);
            qf[s][3] = __float_as_uint(f1.y);
        }
    }

    float o[16][4];
#pragma unroll
    for (int nt = 0; nt < 16; nt++)
#pragma unroll
        for (int r = 0; r < 4; r++) o[nt][r] = 0.f;
    float m0 = -1e30f, m1 = -1e30f, l0 = 0.f, l1 = 0.f;

    const int rowg0 = q0 + wid * 16 + g;
    const int rowg1 = rowg0 + 8;

    for (int j = 0; j < ntiles; j++) {
        if (j + 1 < ntiles) issue_tile(j + 1, (j + 1) & 1);
        asm volatile("cp.async.commit_group;\n");
        asm volatile("cp.async.wait_group 1;\n");
        __syncthreads();

        const int st = j & 1;
        const float* Ks = sm + st * K_STW;
        const float* Vs = sm + V_BASE_W + st * V_STW;

        float sv[8][4];
#pragma unroll
        for (int nt = 0; nt < 8; nt++)
#pragma unroll
            for (int r = 0; r < 4; r++) sv[nt][r] = 0.f;

#pragma unroll
        for (int s = 0; s < 16; s++) {
            const int kof = (8 * s + 2 * c) ^ ((g & 3) * 8);
#pragma unroll
            for (int nt = 0; nt < 8; nt++) {
                float2 kf = *(const float2*)(Ks + (nt * 8 + g) * 128 + kof);
                unsigned bv[2] = {__float_as_uint(kf.x), __float_as_uint(kf.y)};
                mma_tf32(sv[nt], qf[s], bv);
            }
        }

#pragma unroll
        for (int nt = 0; nt < 8; nt++)
#pragma unroll
            for (int r = 0; r < 4; r++) sv[nt][r] *= scale;

        if (j >= 2 * qt) {
            const int kv0 = j * 64;
#pragma unroll
            for (int nt = 0; nt < 8; nt++) {
                const int col = kv0 + nt * 8 + 2 * c;
                if (col     > rowg0) sv[nt][0] = -1e30f;
                if (col + 1 > rowg0) sv[nt][1] = -1e30f;
                if (col     > rowg1) sv[nt][2] = -1e30f;
                if (col + 1 > rowg1) sv[nt][3] = -1e30f;
            }
        }

        float mx0 = -1e30f, mx1 = -1e30f;
#pragma unroll
        for (int nt = 0; nt < 8; nt++) {
            mx0 = fmaxf(mx0, fmaxf(sv[nt][0], sv[nt][1]));
            mx1 = fmaxf(mx1, fmaxf(sv[nt][2], sv[nt][3]));
        }
        mx0 = fmaxf(mx0, __shfl_xor_sync(0xffffffffu, mx0, 1));
        mx0 = fmaxf(mx0, __shfl_xor_sync(0xffffffffu, mx0, 2));
        mx1 = fmaxf(mx1, __shfl_xor_sync(0xffffffffu, mx1, 1));
        mx1 = fmaxf(mx1, __shfl_xor_sync(0xffffffffu, mx1, 2));

        const float mn0 = fmaxf(m0, mx0);
        const float mn1 = fmaxf(m1, mx1);
        const float a0 = __expf(m0 - mn0);
        const float a1 = __expf(m1 - mn1);
        m0 = mn0; m1 = mn1;

        float l0a = 0.f, l1a = 0.f;
        unsigned pf[8][4];
#pragma unroll
        for (int nt = 0; nt < 8; nt++) {
            float p0 = __expf(sv[nt][0] - mn0);
            float p1 = __expf(sv[nt][1] - mn0);
            float p2 = __expf(sv[nt][2] - mn1);
            float p3 = __expf(sv[nt][3] - mn1);
            l0a += p0 + p1;
            l1a += p2 + p3;
            pf[nt][0] = f2tf(p0);
            pf[nt][1] = f2tf(p2);
            pf[nt][2] = f2tf(p1);
            pf[nt][3] = f2tf(p3);
        }
        l0 = l0 * a0 + l0a;
        l1 = l1 * a1 + l1a;

#pragma unroll
        for (int nt = 0; nt < 16; nt++) {
            o[nt][0] *= a0; o[nt][1] *= a0;
            o[nt][2] *= a1; o[nt][3] *= a1;
        }

#pragma unroll
        for (int s = 0; s < 8; s++) {
            const float* vrow = Vs + (8 * s + 2 * c) * 132 + g;
#pragma unroll
            for (int nt = 0; nt < 16; nt++) {
                unsigned bv[2] = {__float_as_uint(vrow[nt * 8]),
                                  __float_as_uint(vrow[nt * 8 + 132])};
                mma_tf32(o[nt], pf[s], bv);
            }
        }
        __syncthreads();
    }

    l0 += __shfl_xor_sync(0xffffffffu, l0, 1);
    l0 += __shfl_xor_sync(0xffffffffu, l0, 2);
    l1 += __shfl_xor_sync(0xffffffffu, l1, 1);
    l1 += __shfl_xor_sync(0xffffffffu, l1, 2);
    const float inv0 = 1.f / l0;
    const float inv1 = 1.f / l1;

    float* c0 = ctx + ((size_t)b * SEQ + rowg0) * HID + (size_t)h * HDIM;
    float* c1 = ctx + ((size_t)b * SEQ + rowg1) * HID + (size_t)h * HDIM;
#pragma unroll
    for (int nt = 0; nt < 16; nt++) {
        const int col = nt * 8 + 2 * c;
        float2 w0, w1;
        w0.x = __uint_as_float(f2tf(o[nt][0] * inv0));
        w0.y = __uint_as_float(f2tf(o[nt][1] * inv0));
        w1.x = __uint_as_float(f2tf(o[nt][2] * inv1));
        w1.y = __uint_as_float(f2tf(o[nt][3] * inv1));
        *(float2*)(c0 + col) = w0;
        *(float2*)(c1 + col) = w1;
    }
}

// ===========================================================================
extern "C" void kernel_launch(void* const* d_in, const int* in_sizes, int n_in,
                              void* d_out, int out_size) {
    const float* x      = (const float*)d_in[0];
    const float* w_qkv  = (const float*)d_in[1];
    const float* b_qkv  = (const float*)d_in[2];
    const float* w_out  = (const float*)d_in[3];
    const float* b_out  = (const float*)d_in[4];
    float* out = (float*)d_out;

    float* qkv; cudaGetSymbolAddress((void**)&qkv, g_qkv);
    float* ctx; cudaGetSymbolAddress((void**)&ctx, g_ctx);
    float* xt;  cudaGetSymbolAddress((void**)&xt,  g_x);
    float* wqT; cudaGetSymbolAddress((void**)&wqT, g_wq);
    float* woT; cudaGetSymbolAddress((void**)&woT, g_wo);

    cudaFuncSetAttribute(sgemm_tf32_kernel<true>,
                         cudaFuncAttributeMaxDynamicSharedMemorySize, G_SMEM_BYTES);
    cudaFuncSetAttribute(sgemm_tf32_kernel<false>,
                         cudaFuncAttributeMaxDynamicSharedMemorySize, G_SMEM_BYTES);
    cudaFuncSetAttribute(flash_attn_tc_kernel,
                         cudaFuncAttributeMaxDynamicSharedMemorySize, AT_SMEM_BYTES);

    // 0) preprocess: truncate x; truncate+transpose weights to [N][K]
    trunc_copy_kernel<<<(MROWS * HID / 4) / 256, 256>>>(
        (const float4*)x, (float4*)xt, MROWS * HID / 4);
    trunc_transpose_kernel<<<dim3(K3 / 32, HID / 32), dim3(32, 8)>>>(w_qkv, wqT, HID, K3);
    trunc_transpose_kernel<<<dim3(HID / 32, HID / 32), dim3(32, 8)>>>(w_out, woT, HID, HID);

    // 1) QKV projection (epilogue truncates -> qkv already tf32 bits)
    sgemm_tf32_kernel<true><<<dim3(K3 / 128, MROWS / 128), 256, G_SMEM_BYTES>>>(
        xt, wqT, b_qkv, qkv, K3, HID);

    // 2) tensor-core causal flash attention (epilogue truncates ctx)
    flash_attn_tc_kernel<<<dim3(SEQ / 128, NHEAD, BATCH), 256, AT_SMEM_BYTES>>>(qkv, ctx);

    // 3) output projection (fp32 out)
    sgemm_tf32_kernel<false><<<dim3(HID / 128, MROWS / 128), 256, G_SMEM_BYTES>>>(
        ctx, woT, b_out, out, HID, HID);
}

// round 15
// speedup vs baseline: 2.4610x; 2.4610x over previous
#include <cuda_runtime.h>
#include <cuda_fp16.h>
#include <cstdint>

// Problem constants
#define BATCH 2
#define SEQ   2048
#define HID   2048
#define NHEAD 16
#define HDIM  128
#define MROWS (BATCH * SEQ)   // 4096
#define K3    (3 * HID)       // 6144

// Scratch (allocation-free rule: __device__ globals)
__device__ float  g_qkv[(size_t)MROWS * K3];    // fp32 (tf32 bits) for attention
__device__ __half g_xh [(size_t)MROWS * HID];   // x, half, k-permuted
__device__ __half g_wqh[(size_t)K3 * HID];      // w_qkv^T [6144][2048] half, k-perm
__device__ __half g_woh[(size_t)HID * HID];     // w_out^T [2048][2048] half, k-perm
__device__ __half g_cth[(size_t)MROWS * HID];   // ctx, half, k-permuted

__device__ __forceinline__ unsigned f2tf(float x) {
    unsigned u;
    asm("cvt.rna.tf32.f32 %0, %1;" : "=r"(u) : "f"(x));
    return u;
}

__device__ __forceinline__ void mma_tf32(float* d, const unsigned* a, const unsigned* b) {
    asm volatile(
        "mma.sync.aligned.m16n8k8.row.col.f32.tf32.tf32.f32 "
        "{%0,%1,%2,%3},{%4,%5,%6,%7},{%8,%9},{%0,%1,%2,%3};"
        : "+f"(d[0]), "+f"(d[1]), "+f"(d[2]), "+f"(d[3])
        : "r"(a[0]), "r"(a[1]), "r"(a[2]), "r"(a[3]), "r"(b[0]), "r"(b[1]));
}

__device__ __forceinline__ void mma_f16(float* d, const unsigned* a, const unsigned* b) {
    asm volatile(
        "mma.sync.aligned.m16n8k16.row.col.f32.f16.f16.f32 "
        "{%0,%1,%2,%3},{%4,%5,%6,%7},{%8,%9},{%0,%1,%2,%3};"
        : "+f"(d[0]), "+f"(d[1]), "+f"(d[2]), "+f"(d[3])
        : "r"(a[0]), "r"(a[1]), "r"(a[2]), "r"(a[3]), "r"(b[0]), "r"(b[1]));
}

__device__ __forceinline__ void cp16(unsigned dst, const void* src) {
    asm volatile("cp.async.cg.shared.global [%0], [%1], 16;\n" :: "r"(dst), "l"(src));
}

__device__ __forceinline__ void lds64(unsigned& lo, unsigned& hi, unsigned addr) {
    asm volatile("ld.shared.v2.b32 {%0,%1}, [%2];" : "=r"(lo), "=r"(hi) : "r"(addr));
}

// k-permutation within a 16-block: k -> pos so that lane c's halves
// {2c,2c+1,2c+8,2c+9} are contiguous 8 bytes at pos 4c.
__device__ __forceinline__ int kperm(int k) {
    int kk = k & 15;
    int pos = (kk < 8) ? (((kk >> 1) << 2) | (kk & 1))
                       : ((((kk - 8) >> 1) << 2) + 2 + (kk & 1));
    return (k & ~15) | pos;
}

// ===========================================================================
// Preprocessing
// ===========================================================================
// fp32 [R][C] -> half [R][C] with k-permutation (pairs stay contiguous)
__global__ void h16_perm_copy(const float2* __restrict__ src,
                              __half2* __restrict__ dst, int n2, int Chalf) {
    int i = blockIdx.x * blockDim.x + threadIdx.x;
    if (i >= n2) return;
    float2 v = src[i];
    int r = i / Chalf;
    int k = (i - r * Chalf) * 2;
    int kk = k & 15;
    int pos = (kk < 8) ? ((kk >> 1) << 2) : ((((kk - 8) >> 1) << 2) + 2);
    dst[((size_t)r * (Chalf * 2) + (k & ~15) + pos) >> 1] = __floats2half2_rn(v.x, v.y);
}

// fp32 src[R][C] -> half dst[C][R] with R-dim (k) permutation
__global__ void h16_perm_transpose(const float* __restrict__ src,
                                   __half* __restrict__ dst, int R, int C) {
    __shared__ float t[32][33];
    const int c0 = blockIdx.x * 32, r0 = blockIdx.y * 32;
    const int tx = threadIdx.x, ty = threadIdx.y;
#pragma unroll
    for (int j = 0; j < 32; j += 8)
        t[ty + j][tx] = src[(size_t)(r0 + ty + j) * C + c0 + tx];
    __syncthreads();
#pragma unroll
    for (int j = 0; j < 32; j += 8) {
        int n = c0 + ty + j;
        int k = r0 + tx;
        dst[(size_t)n * R + kperm(k)] = __float2half_rn(t[tx][ty + j]);
    }
}

// ===========================================================================
// fp16 mma.sync GEMM: C[M,N] = A[M,K] @ Bt[N,K]^T + bias
// Block 128x128, BK=32, 256 threads (8 warps 2m x 4n, warp tile 64x32).
// A/B smem: 128 rows x 64B (32 half, k-permuted), 16B-chunk XOR(row&3) swizzle.
// Fragments: one LDS.64 per row per k16-step (canonical m16n8k16 layout).
// 3-stage cp.async pipeline, one __syncthreads per iter.
// ===========================================================================
#define HSTAGE_B 16384
#define HG_SMEM_BYTES (3 * HSTAGE_B)   // 49152

template <bool TRUNC_OUT>
__global__ __launch_bounds__(256, 2)
void hgemm_kernel(const __half* __restrict__ A, const __half* __restrict__ Bt,
                  const float* __restrict__ bias, float* __restrict__ C,
                  int N, int K) {
    extern __shared__ char smc[];
    const int tid = threadIdx.x;
    const int lane = tid & 31;
    const int warp = tid >> 5;
    const int wm = warp & 1;
    const int wn = warp >> 1;
    const int bm = blockIdx.y * 128;
    const int bn = blockIdx.x * 128;

    const int g = lane >> 2;
    const int c = lane & 3;

    unsigned smu;
    { unsigned long long p = __cvta_generic_to_shared(smc); smu = (unsigned)p; }

    // copy mapping: per stage A 512 chunks, B 512 chunks; 2+2 per thread
    unsigned aDst[2], bDst[2];
    const __half* aSrc[2];
    const __half* bSrc[2];
#pragma unroll
    for (int r = 0; r < 2; r++) {
        int a = tid + 256 * r;
        int row = a >> 2, cc = a & 3;
        unsigned sw = (unsigned)(row * 64 + ((cc ^ (row & 3)) << 4));
        aDst[r] = smu + sw;
        bDst[r] = smu + 8192u + sw;
        aSrc[r] = A  + (size_t)(bm + row) * K + cc * 8;
        bSrc[r] = Bt + (size_t)(bn + row) * K + cc * 8;
    }

    // fragment base addresses (stage-relative, kstep0)
    unsigned aRel[4], bRel[4];
    const unsigned csub = (unsigned)((((c >> 1) ^ (g & 3)) << 4) + (c & 1) * 8);
#pragma unroll
    for (int mt = 0; mt < 4; mt++) {
        int row = wm * 64 + mt * 16 + g;
        aRel[mt] = (unsigned)(row * 64) + csub;
    }
#pragma unroll
    for (int nt = 0; nt < 4; nt++) {
        int row = wn * 32 + nt * 8 + g;
        bRel[nt] = 8192u + (unsigned)(row * 64) + csub;
    }

    float acc[4][4][4];
#pragma unroll
    for (int mt = 0; mt < 4; mt++)
#pragma unroll
        for (int nt = 0; nt < 4; nt++)
#pragma unroll
            for (int r = 0; r < 4; r++) acc[mt][nt][r] = 0.f;

    const int T = K / 32;

    auto issue = [&](int i) {
        const unsigned so = (unsigned)((i % 3) * HSTAGE_B);
        const int k0 = i * 32;
#pragma unroll
        for (int r = 0; r < 2; r++) {
            cp16(aDst[r] + so, aSrc[r] + k0);
            cp16(bDst[r] + so, bSrc[r] + k0);
        }
    };

    issue(0);
    asm volatile("cp.async.commit_group;\n");
    issue(1);
    asm volatile("cp.async.commit_group;\n");

    for (int i = 0; i < T; i++) {
        asm volatile("cp.async.wait_group 1;\n");
        __syncthreads();

        if (i + 2 < T) issue(i + 2);
        asm volatile("cp.async.commit_group;\n");

        const unsigned stage = smu + (unsigned)((i % 3) * HSTAGE_B);

#pragma unroll
        for (int ks = 0; ks < 2; ks++) {
            const unsigned kx = ks ? 32u : 0u;
            unsigned av[4][4];
#pragma unroll
            for (int mt = 0; mt < 4; mt++) {
                lds64(av[mt][0], av[mt][2], (stage + aRel[mt]) ^ kx);
                lds64(av[mt][1], av[mt][3], (stage + aRel[mt] + 512u) ^ kx);
            }
            unsigned bv[4][2];
#pragma unroll
            for (int nt = 0; nt < 4; nt++)
                lds64(bv[nt][0], bv[nt][1], (stage + bRel[nt]) ^ kx);
#pragma unroll
            for (int mt = 0; mt < 4; mt++)
#pragma unroll
                for (int nt = 0; nt < 4; nt++)
                    mma_f16(acc[mt][nt], av[mt], bv[nt]);
        }
    }

    // epilogue: add bias, write float2 pairs (cols 2c, 2c+1)
#pragma unroll
    for (int mt = 0; mt < 4; mt++) {
        const int row = bm + wm * 64 + mt * 16 + g;
#pragma unroll
        for (int nt = 0; nt < 4; nt++) {
            const int col = bn + wn * 32 + nt * 8 + 2 * c;
            const float b0 = __ldg(&bias[col]);
            const float b1 = __ldg(&bias[col + 1]);
            float v00 = acc[mt][nt][0] + b0, v01 = acc[mt][nt][1] + b1;
            float v10 = acc[mt][nt][2] + b0, v11 = acc[mt][nt][3] + b1;
            if (TRUNC_OUT) {
                v00 = __uint_as_float(f2tf(v00));
                v01 = __uint_as_float(f2tf(v01));
                v10 = __uint_as_float(f2tf(v10));
                v11 = __uint_as_float(f2tf(v11));
            }
            float2 o0 = {v00, v01}, o1 = {v10, v11};
            *(float2*)(C + (size_t)row * N + col) = o0;
            *(float2*)(C + (size_t)(row + 8) * N + col) = o1;
        }
    }
}

// ===========================================================================
// Tensor-core causal flash attention (tf32 mma.sync) — R13 mainloop;
// epilogue writes ctx as k-permuted half (feeds fp16 out-projection).
// ===========================================================================
#define K_STW 8192
#define V_STW 8448
#define V_BASE_W 16384
#define AT_SMEM_BYTES ((V_BASE_W + 2 * V_STW) * 4)   // 133120

__global__ __launch_bounds__(256, 1)
void flash_attn_tc_kernel(const float* __restrict__ qkv, __half* __restrict__ ctxh) {
    extern __shared__ float sm[];
    const int tid = threadIdx.x;
    const int lane = tid & 31;
    const int wid = tid >> 5;
    const int g = lane >> 2;
    const int c = lane & 3;
    const int qt = 15 - blockIdx.x;
    const int h = blockIdx.y;
    const int b = blockIdx.z;
    const int q0 = qt * 128;
    const float scale = 0.08838834764831845f;

    const float* base = qkv + ((size_t)b * SEQ) * K3 + (size_t)h * (3 * HDIM);

    unsigned smu;
    { unsigned long long p = __cvta_generic_to_shared(sm); smu = (unsigned)p; }

    const int ntiles = 2 * qt + 2;

    auto issue_tile = [&](int j, int st) {
        const float* kvb = base + (size_t)(j * 64) * K3;
#pragma unroll
        for (int r = 0; r < 8; r++) {
            int chunk = tid + 256 * r;
            int row = chunk >> 5;
            int cw = (chunk & 31) * 4;
            const float* src = kvb + (size_t)row * K3 + cw;
            unsigned kd = smu + (unsigned)(st * K_STW + row * 128 + (cw ^ ((row & 3) * 8))) * 4;
            unsigned vd = smu + (unsigned)(V_BASE_W + st * V_STW + row * 132 + cw) * 4;
            cp16(kd, src + HDIM);
            cp16(vd, src + 2 * HDIM);
        }
    };

    issue_tile(0, 0);
    asm volatile("cp.async.commit_group;\n");

    unsigned qf[16][4];
    {
        const float* qrow = base + (size_t)(q0 + wid * 16 + g) * K3;
        const float* qrow8 = qrow + 8 * (size_t)K3;
#pragma unroll
        for (int s = 0; s < 16; s++) {
            float2 f0 = *(const float2*)(qrow + 8 * s + 2 * c);
            float2 f1 = *(const float2*)(qrow8 + 8 * s + 2 * c);
            qf[s][0] = __float_as_uint(f0.x);
            qf[s][2] = __float_as_uint(f0.y);
            qf[s][1] = __float_as_uint(f1.x);
            qf[s][3] = __float_as_uint(f1.y);
        }
    }

    float o[16][4];
#pragma unroll
    for (int nt = 0; nt < 16; nt++)
#pragma unroll
        for (int r = 0; r < 4; r++) o[nt][r] = 0.f;
    float m0 = -1e30f, m1 = -1e30f, l0 = 0.f, l1 = 0.f;

    const int rowg0 = q0 + wid * 16 + g;
    const int rowg1 = rowg0 + 8;

    for (int j = 0; j < ntiles; j++) {
        if (j + 1 < ntiles) issue_tile(j + 1, (j + 1) & 1);
        asm volatile("cp.async.commit_group;\n");
        asm volatile("cp.async.wait_group 1;\n");
        __syncthreads();

        const int st = j & 1;
        const float* Ks = sm + st * K_STW;
        const float* Vs = sm + V_BASE_W + st * V_STW;

        float sv[8][4];
#pragma unroll
        for (int nt = 0; nt < 8; nt++)
#pragma unroll
            for (int r = 0; r < 4; r++) sv[nt][r] = 0.f;

#pragma unroll
        for (int s = 0; s < 16; s++) {
            const int kof = (8 * s + 2 * c) ^ ((g & 3) * 8);
#pragma unroll
            for (int nt = 0; nt < 8; nt++) {
                float2 kf = *(const float2*)(Ks + (nt * 8 + g) * 128 + kof);
                unsigned bv[2] = {__float_as_uint(kf.x), __float_as_uint(kf.y)};
                mma_tf32(sv[nt], qf[s], bv);
            }
        }

#pragma unroll
        for (int nt = 0; nt < 8; nt++)
#pragma unroll
            for (int r = 0; r < 4; r++) sv[nt][r] *= scale;

        if (j >= 2 * qt) {
            const int kv0 = j * 64;
#pragma unroll
            for (int nt = 0; nt < 8; nt++) {
                const int col = kv0 + nt * 8 + 2 * c;
                if (col     > rowg0) sv[nt][0] = -1e30f;
                if (col + 1 > rowg0) sv[nt][1] = -1e30f;
                if (col     > rowg1) sv[nt][2] = -1e30f;
                if (col + 1 > rowg1) sv[nt][3] = -1e30f;
            }
        }

        float mx0 = -1e30f, mx1 = -1e30f;
#pragma unroll
        for (int nt = 0; nt < 8; nt++) {
            mx0 = fmaxf(mx0, fmaxf(sv[nt][0], sv[nt][1]));
            mx1 = fmaxf(mx1, fmaxf(sv[nt][2], sv[nt][3]));
        }
        mx0 = fmaxf(mx0, __shfl_xor_sync(0xffffffffu, mx0, 1));
        mx0 = fmaxf(mx0, __shfl_xor_sync(0xffffffffu, mx0, 2));
        mx1 = fmaxf(mx1, __shfl_xor_sync(0xffffffffu, mx1, 1));
        mx1 = fmaxf(mx1, __shfl_xor_sync(0xffffffffu, mx1, 2));

        const float mn0 = fmaxf(m0, mx0);
        const float mn1 = fmaxf(m1, mx1);
        const float a0 = __expf(m0 - mn0);
        const float a1 = __expf(m1 - mn1);
        m0 = mn0; m1 = mn1;

        float l0a = 0.f, l1a = 0.f;
        unsigned pf[8][4];
#pragma unroll
        for (int nt = 0; nt < 8; nt++) {
            float p0 = __expf(sv[nt][0] - mn0);
            float p1 = __expf(sv[nt][1] - mn0);
            float p2 = __expf(sv[nt][2] - mn1);
            float p3 = __expf(sv[nt][3] - mn1);
            l0a += p0 + p1;
            l1a += p2 + p3;
            pf[nt][0] = f2tf(p0);
            pf[nt][1] = f2tf(p2);
            pf[nt][2] = f2tf(p1);
            pf[nt][3] = f2tf(p3);
        }
        l0 = l0 * a0 + l0a;
        l1 = l1 * a1 + l1a;

#pragma unroll
        for (int nt = 0; nt < 16; nt++) {
            o[nt][0] *= a0; o[nt][1] *= a0;
            o[nt][2] *= a1; o[nt][3] *= a1;
        }

#pragma unroll
        for (int s = 0; s < 8; s++) {
            const float* vrow = Vs + (8 * s + 2 * c) * 132 + g;
#pragma unroll
            for (int nt = 0; nt < 16; nt++) {
                unsigned bv[2] = {__float_as_uint(vrow[nt * 8]),
                                  __float_as_uint(vrow[nt * 8 + 132])};
                mma_tf32(o[nt], pf[s], bv);
            }
        }
        __syncthreads();
    }

    l0 += __shfl_xor_sync(0xffffffffu, l0, 1);
    l0 += __shfl_xor_sync(0xffffffffu, l0, 2);
    l1 += __shfl_xor_sync(0xffffffffu, l1, 1);
    l1 += __shfl_xor_sync(0xffffffffu, l1, 2);
    const float inv0 = 1.f / l0;
    const float inv1 = 1.f / l1;

    // epilogue: write ctx as k-permuted half
    __half* c0h = ctxh + ((size_t)b * SEQ + rowg0) * HID + (size_t)h * HDIM;
    __half* c1h = ctxh + ((size_t)b * SEQ + rowg1) * HID + (size_t)h * HDIM;
#pragma unroll
    for (int nt = 0; nt < 16; nt++) {
        const int Ccol = nt * 8 + 2 * c;   // even
        const int kk = Ccol & 15;
        const int pos = (kk < 8) ? ((kk >> 1) << 2) : ((((kk - 8) >> 1) << 2) + 2);
        const int col = (Ccol & ~15) + pos;   // even
        __half2 h0 = __floats2half2_rn(o[nt][0] * inv0, o[nt][1] * inv0);
        __half2 h1 = __floats2half2_rn(o[nt][2] * inv1, o[nt][3] * inv1);
        *(__half2*)(c0h + col) = h0;
        *(__half2*)(c1h + col) = h1;
    }
}

// ===========================================================================
extern "C" void kernel_launch(void* const* d_in, const int* in_sizes, int n_in,
                              void* d_out, int out_size) {
    const float* x      = (const float*)d_in[0];
    const float* w_qkv  = (const float*)d_in[1];
    const float* b_qkv  = (const float*)d_in[2];
    const float* w_out  = (const float*)d_in[3];
    const float* b_out  = (const float*)d_in[4];
    float* out = (float*)d_out;

    float*  qkv; cudaGetSymbolAddress((void**)&qkv, g_qkv);
    __half* xh;  cudaGetSymbolAddress((void**)&xh,  g_xh);
    __half* wqh; cudaGetSymbolAddress((void**)&wqh, g_wqh);
    __half* woh; cudaGetSymbolAddress((void**)&woh, g_woh);
    __half* cth; cudaGetSymbolAddress((void**)&cth, g_cth);

    cudaFuncSetAttribute(hgemm_kernel<true>,
                         cudaFuncAttributeMaxDynamicSharedMemorySize, HG_SMEM_BYTES);
    cudaFuncSetAttribute(hgemm_kernel<false>,
                         cudaFuncAttributeMaxDynamicSharedMemorySize, HG_SMEM_BYTES);
    cudaFuncSetAttribute(flash_attn_tc_kernel,
                         cudaFuncAttributeMaxDynamicSharedMemorySize, AT_SMEM_BYTES);

    // 0) preprocess: x -> half (k-perm); weights -> half transposed (k-perm)
    {
        int n2 = MROWS * HID / 2;
        h16_perm_copy<<<n2 / 256, 256>>>((const float2*)x, (__half2*)xh, n2, HID / 2);
        h16_perm_transpose<<<dim3(K3 / 32, HID / 32), dim3(32, 8)>>>(w_qkv, wqh, HID, K3);
        h16_perm_transpose<<<dim3(HID / 32, HID / 32), dim3(32, 8)>>>(w_out, woh, HID, HID);
    }

    // 1) QKV projection (fp16 mma; epilogue truncates to tf32 bits for attention)
    hgemm_kernel<true><<<dim3(K3 / 128, MROWS / 128), 256, HG_SMEM_BYTES>>>(
        xh, wqh, b_qkv, qkv, K3, HID);

    // 2) tf32 tensor-core causal flash attention (epilogue -> permuted half ctx)
    flash_attn_tc_kernel<<<dim3(SEQ / 128, NHEAD, BATCH), 256, AT_SMEM_BYTES>>>(qkv, cth);

    // 3) output projection (fp16 mma, fp32 out)
    hgemm_kernel<false><<<dim3(HID / 128, MROWS / 128), 256, HG_SMEM_BYTES>>>(
        cth, woh, b_out, out, HID, HID);
}

// round 16
// speedup vs baseline: 2.5620x; 1.0410x over previous
#include <cuda_runtime.h>
#include <cuda_fp16.h>
#include <cstdint>

// Problem constants
#define BATCH 2
#define SEQ   2048
#define HID   2048
#define NHEAD 16
#define HDIM  128
#define MROWS (BATCH * SEQ)   // 4096
#define K3    (3 * HID)       // 6144

// Scratch (allocation-free rule: __device__ globals)
__device__ float  g_qkv [(size_t)MROWS * K3];   // fp32 (tf32 bits): V for attention
__device__ __half g_qkvh[(size_t)MROWS * K3];   // half, k-permuted: Q/K for attention
__device__ __half g_xh [(size_t)MROWS * HID];   // x, half, k-permuted
__device__ __half g_wqh[(size_t)K3 * HID];      // w_qkv^T half, k-perm
__device__ __half g_woh[(size_t)HID * HID];     // w_out^T half, k-perm
__device__ __half g_cth[(size_t)MROWS * HID];   // ctx, half, k-permuted

__device__ __forceinline__ unsigned f2tf(float x) {
    unsigned u;
    asm("cvt.rna.tf32.f32 %0, %1;" : "=r"(u) : "f"(x));
    return u;
}

__device__ __forceinline__ void mma_tf32(float* d, const unsigned* a, const unsigned* b) {
    asm volatile(
        "mma.sync.aligned.m16n8k8.row.col.f32.tf32.tf32.f32 "
        "{%0,%1,%2,%3},{%4,%5,%6,%7},{%8,%9},{%0,%1,%2,%3};"
        : "+f"(d[0]), "+f"(d[1]), "+f"(d[2]), "+f"(d[3])
        : "r"(a[0]), "r"(a[1]), "r"(a[2]), "r"(a[3]), "r"(b[0]), "r"(b[1]));
}

__device__ __forceinline__ void mma_f16(float* d, const unsigned* a, const unsigned* b) {
    asm volatile(
        "mma.sync.aligned.m16n8k16.row.col.f32.f16.f16.f32 "
        "{%0,%1,%2,%3},{%4,%5,%6,%7},{%8,%9},{%0,%1,%2,%3};"
        : "+f"(d[0]), "+f"(d[1]), "+f"(d[2]), "+f"(d[3])
        : "r"(a[0]), "r"(a[1]), "r"(a[2]), "r"(a[3]), "r"(b[0]), "r"(b[1]));
}

__device__ __forceinline__ void cp16(unsigned dst, const void* src) {
    asm volatile("cp.async.cg.shared.global [%0], [%1], 16;\n" :: "r"(dst), "l"(src));
}

__device__ __forceinline__ void lds64(unsigned& lo, unsigned& hi, unsigned addr) {
    asm volatile("ld.shared.v2.b32 {%0,%1}, [%2];" : "=r"(lo), "=r"(hi) : "r"(addr));
}

// k-permutation within a 16-block (even kk): pairs {2c,2c+1}->4c, {2c+8,2c+9}->4c+2
__device__ __forceinline__ int kperm_even(int kk) {
    return (kk < 8) ? ((kk >> 1) << 2) : ((((kk - 8) >> 1) << 2) + 2);
}

// ===========================================================================
// Preprocessing
// ===========================================================================
__global__ void h16_perm_copy(const float2* __restrict__ src,
                              __half2* __restrict__ dst, int n2, int Chalf) {
    int i = blockIdx.x * blockDim.x + threadIdx.x;
    if (i >= n2) return;
    float2 v = src[i];
    int r = i / Chalf;
    int k = (i - r * Chalf) * 2;
    int pos = kperm_even(k & 15);
    dst[((size_t)r * (Chalf * 2) + (k & ~15) + pos) >> 1] = __floats2half2_rn(v.x, v.y);
}

__global__ void h16_perm_transpose(const float* __restrict__ src,
                                   __half* __restrict__ dst, int R, int C) {
    __shared__ float t[32][33];
    const int c0 = blockIdx.x * 32, r0 = blockIdx.y * 32;
    const int tx = threadIdx.x, ty = threadIdx.y;
#pragma unroll
    for (int j = 0; j < 32; j += 8)
        t[ty + j][tx] = src[(size_t)(r0 + ty + j) * C + c0 + tx];
    __syncthreads();
#pragma unroll
    for (int j = 0; j < 32; j += 8) {
        int n = c0 + ty + j;
        int k = r0 + tx;
        int kk = k & 15;
        int pos = (kk < 8) ? (((kk >> 1) << 2) | (kk & 1))
                           : ((((kk - 8) >> 1) << 2) + 2 + (kk & 1));
        dst[(size_t)n * R + (k & ~15) + pos] = __float2half_rn(t[tx][ty + j]);
    }
}

// ===========================================================================
// fp16 mma.sync GEMM (R15 structure). TRUNC_OUT additionally writes the
// half k-permuted copy Ch (for attention Q/K) and truncates fp32 to tf32.
// ===========================================================================
#define HSTAGE_B 16384
#define HG_SMEM_BYTES (3 * HSTAGE_B)   // 49152

template <bool TRUNC_OUT>
__global__ __launch_bounds__(256, 2)
void hgemm_kernel(const __half* __restrict__ A, const __half* __restrict__ Bt,
                  const float* __restrict__ bias, float* __restrict__ C,
                  __half* __restrict__ Ch, int N, int K) {
    extern __shared__ char smc[];
    const int tid = threadIdx.x;
    const int lane = tid & 31;
    const int warp = tid >> 5;
    const int wm = warp & 1;
    const int wn = warp >> 1;
    const int bm = blockIdx.y * 128;
    const int bn = blockIdx.x * 128;

    const int g = lane >> 2;
    const int c = lane & 3;

    unsigned smu;
    { unsigned long long p = __cvta_generic_to_shared(smc); smu = (unsigned)p; }

    unsigned aDst[2], bDst[2];
    const __half* aSrc[2];
    const __half* bSrc[2];
#pragma unroll
    for (int r = 0; r < 2; r++) {
        int a = tid + 256 * r;
        int row = a >> 2, cc = a & 3;
        unsigned sw = (unsigned)(row * 64 + ((cc ^ (row & 3)) << 4));
        aDst[r] = smu + sw;
        bDst[r] = smu + 8192u + sw;
        aSrc[r] = A  + (size_t)(bm + row) * K + cc * 8;
        bSrc[r] = Bt + (size_t)(bn + row) * K + cc * 8;
    }

    unsigned aRel[4], bRel[4];
    const unsigned csub = (unsigned)((((c >> 1) ^ (g & 3)) << 4) + (c & 1) * 8);
#pragma unroll
    for (int mt = 0; mt < 4; mt++)
        aRel[mt] = (unsigned)((wm * 64 + mt * 16 + g) * 64) + csub;
#pragma unroll
    for (int nt = 0; nt < 4; nt++)
        bRel[nt] = 8192u + (unsigned)((wn * 32 + nt * 8 + g) * 64) + csub;

    float acc[4][4][4];
#pragma unroll
    for (int mt = 0; mt < 4; mt++)
#pragma unroll
        for (int nt = 0; nt < 4; nt++)
#pragma unroll
            for (int r = 0; r < 4; r++) acc[mt][nt][r] = 0.f;

    const int T = K / 32;

    auto issue = [&](int i) {
        const unsigned so = (unsigned)((i % 3) * HSTAGE_B);
        const int k0 = i * 32;
#pragma unroll
        for (int r = 0; r < 2; r++) {
            cp16(aDst[r] + so, aSrc[r] + k0);
            cp16(bDst[r] + so, bSrc[r] + k0);
        }
    };

    issue(0);
    asm volatile("cp.async.commit_group;\n");
    issue(1);
    asm volatile("cp.async.commit_group;\n");

    for (int i = 0; i < T; i++) {
        asm volatile("cp.async.wait_group 1;\n");
        __syncthreads();

        if (i + 2 < T) issue(i + 2);
        asm volatile("cp.async.commit_group;\n");

        const unsigned stage = smu + (unsigned)((i % 3) * HSTAGE_B);

#pragma unroll
        for (int ks = 0; ks < 2; ks++) {
            const unsigned kx = ks ? 32u : 0u;
            unsigned av[4][4];
#pragma unroll
            for (int mt = 0; mt < 4; mt++) {
                lds64(av[mt][0], av[mt][2], (stage + aRel[mt]) ^ kx);
                lds64(av[mt][1], av[mt][3], (stage + aRel[mt] + 512u) ^ kx);
            }
            unsigned bv[4][2];
#pragma unroll
            for (int nt = 0; nt < 4; nt++)
                lds64(bv[nt][0], bv[nt][1], (stage + bRel[nt]) ^ kx);
#pragma unroll
            for (int mt = 0; mt < 4; mt++)
#pragma unroll
                for (int nt = 0; nt < 4; nt++)
                    mma_f16(acc[mt][nt], av[mt], bv[nt]);
        }
    }

    // epilogue
#pragma unroll
    for (int mt = 0; mt < 4; mt++) {
        const int row = bm + wm * 64 + mt * 16 + g;
#pragma unroll
        for (int nt = 0; nt < 4; nt++) {
            const int col = bn + wn * 32 + nt * 8 + 2 * c;
            const float b0 = __ldg(&bias[col]);
            const float b1 = __ldg(&bias[col + 1]);
            float v00 = acc[mt][nt][0] + b0, v01 = acc[mt][nt][1] + b1;
            float v10 = acc[mt][nt][2] + b0, v11 = acc[mt][nt][3] + b1;
            if (TRUNC_OUT) {
                // half k-permuted copy for attention Q/K
                const int colp = (col & ~15) + kperm_even(col & 15);
                *(__half2*)(Ch + (size_t)row * N + colp) = __floats2half2_rn(v00, v01);
                *(__half2*)(Ch + (size_t)(row + 8) * N + colp) = __floats2half2_rn(v10, v11);
                v00 = __uint_as_float(f2tf(v00));
                v01 = __uint_as_float(f2tf(v01));
                v10 = __uint_as_float(f2tf(v10));
                v11 = __uint_as_float(f2tf(v11));
            }
            float2 o0 = {v00, v01}, o1 = {v10, v11};
            *(float2*)(C + (size_t)row * N + col) = o0;
            *(float2*)(C + (size_t)(row + 8) * N + col) = o1;
        }
    }
}

// ===========================================================================
// Causal flash attention: QK in fp16 (half K smem, k-permuted), PV in tf32.
// S accumulator layout identical for m16n8k16-f16 and m16n8k8-tf32, so the
// softmax + S->P fragment reuse is unchanged from R13/R15.
// smem: K half [2 stages][4 groups][64 rows][64B swizzled] = 16KB/stage,
//       V fp32 [2 stages][64][132] = 33792B/stage.
// ===========================================================================
#define KH_STB 16384
#define V_BASE_B 32768
#define V_STB 33792
#define AT_SMEM_BYTES (V_BASE_B + 2 * V_STB)   // 100352

__global__ __launch_bounds__(256, 1)
void flash_attn_tc_kernel(const float* __restrict__ qkv,
                          const __half* __restrict__ qkvh,
                          __half* __restrict__ ctxh) {
    extern __shared__ char smc[];
    const int tid = threadIdx.x;
    const int lane = tid & 31;
    const int wid = tid >> 5;
    const int g = lane >> 2;
    const int c = lane & 3;
    const int qt = 15 - blockIdx.x;
    const int h = blockIdx.y;
    const int b = blockIdx.z;
    const int q0 = qt * 128;
    const float scale = 0.08838834764831845f;

    const float*  base32 = qkv  + ((size_t)b * SEQ) * K3 + (size_t)h * (3 * HDIM);
    const __half* baseh  = qkvh + ((size_t)b * SEQ) * K3 + (size_t)h * (3 * HDIM);

    unsigned smu;
    { unsigned long long p = __cvta_generic_to_shared(smc); smu = (unsigned)p; }

    const int ntiles = 2 * qt + 2;

    auto issue_tile = [&](int j, int st) {
        // K (half, k-permuted): 64 rows x 16 chunks of 16B
#pragma unroll
        for (int r = 0; r < 4; r++) {
            int a = tid + 256 * r;
            int row = a >> 4, cc = a & 15;
            const __half* src = baseh + (size_t)(j * 64 + row) * K3 + HDIM + cc * 8;
            unsigned kd = smu + (unsigned)(st * KH_STB + (cc >> 2) * 4096 + row * 64 +
                                           (((cc & 3) ^ (row & 3)) << 4));
            cp16(kd, src);
        }
        // V (fp32): 64 rows x 32 chunks of 16B
#pragma unroll
        for (int r = 0; r < 8; r++) {
            int chunk = tid + 256 * r;
            int row = chunk >> 5;
            int cw = (chunk & 31) * 4;
            const float* src = base32 + (size_t)(j * 64 + row) * K3 + 2 * HDIM + cw;
            unsigned vd = smu + (unsigned)(V_BASE_B + st * V_STB + row * 528 + cw * 4);
            cp16(vd, src);
        }
    };

    issue_tile(0, 0);
    asm volatile("cp.async.commit_group;\n");

    // Q fragments (half, k-permuted): 8 k16-steps, 4 regs each
    unsigned qf[8][4];
    {
        const __half* qrow  = baseh + (size_t)(q0 + wid * 16 + g) * K3;
        const __half* qrow8 = qrow + 8 * (size_t)K3;
#pragma unroll
        for (int s = 0; s < 8; s++) {
            uint2 u0 = *(const uint2*)(qrow  + s * 16 + 4 * c);
            uint2 u1 = *(const uint2*)(qrow8 + s * 16 + 4 * c);
            qf[s][0] = u0.x; qf[s][2] = u0.y;
            qf[s][1] = u1.x; qf[s][3] = u1.y;
        }
    }

    float o[16][4];
#pragma unroll
    for (int nt = 0; nt < 16; nt++)
#pragma unroll
        for (int r = 0; r < 4; r++) o[nt][r] = 0.f;
    float m0 = -1e30f, m1 = -1e30f, l0 = 0.f, l1 = 0.f;

    const int rowg0 = q0 + wid * 16 + g;
    const int rowg1 = rowg0 + 8;

    const unsigned csub = (unsigned)((((c >> 1) ^ (g & 3)) << 4) + (c & 1) * 8);

    for (int j = 0; j < ntiles; j++) {
        if (j + 1 < ntiles) issue_tile(j + 1, (j + 1) & 1);
        asm volatile("cp.async.commit_group;\n");
        asm volatile("cp.async.wait_group 1;\n");
        __syncthreads();

        const int st = j & 1;
        const unsigned Kst = smu + (unsigned)(st * KH_STB);
        const float* Vs = (const float*)(smc + V_BASE_B + st * V_STB);

        // ---- S = Q @ K^T (fp16, m16n8k16) ----
        float sv[8][4];
#pragma unroll
        for (int nt = 0; nt < 8; nt++)
#pragma unroll
            for (int r = 0; r < 4; r++) sv[nt][r] = 0.f;

#pragma unroll
        for (int s = 0; s < 8; s++) {
            const unsigned gbase = Kst + (unsigned)((s >> 1) * 4096);
            const unsigned kx = (s & 1) ? 32u : 0u;
#pragma unroll
            for (int nt = 0; nt < 8; nt++) {
                unsigned bv[2];
                lds64(bv[0], bv[1], (gbase + (unsigned)((nt * 8 + g) * 64) + csub) ^ kx);
                mma_f16(sv[nt], qf[s], bv);
            }
        }

#pragma unroll
        for (int nt = 0; nt < 8; nt++)
#pragma unroll
            for (int r = 0; r < 4; r++) sv[nt][r] *= scale;

        if (j >= 2 * qt) {
            const int kv0 = j * 64;
#pragma unroll
            for (int nt = 0; nt < 8; nt++) {
                const int col = kv0 + nt * 8 + 2 * c;
                if (col     > rowg0) sv[nt][0] = -1e30f;
                if (col + 1 > rowg0) sv[nt][1] = -1e30f;
                if (col     > rowg1) sv[nt][2] = -1e30f;
                if (col + 1 > rowg1) sv[nt][3] = -1e30f;
            }
        }

        float mx0 = -1e30f, mx1 = -1e30f;
#pragma unroll
        for (int nt = 0; nt < 8; nt++) {
            mx0 = fmaxf(mx0, fmaxf(sv[nt][0], sv[nt][1]));
            mx1 = fmaxf(mx1, fmaxf(sv[nt][2], sv[nt][3]));
        }
        mx0 = fmaxf(mx0, __shfl_xor_sync(0xffffffffu, mx0, 1));
        mx0 = fmaxf(mx0, __shfl_xor_sync(0xffffffffu, mx0, 2));
        mx1 = fmaxf(mx1, __shfl_xor_sync(0xffffffffu, mx1, 1));
        mx1 = fmaxf(mx1, __shfl_xor_sync(0xffffffffu, mx1, 2));

        const float mn0 = fmaxf(m0, mx0);
        const float mn1 = fmaxf(m1, mx1);
        const float a0 = __expf(m0 - mn0);
        const float a1 = __expf(m1 - mn1);
        m0 = mn0; m1 = mn1;

        float l0a = 0.f, l1a = 0.f;
        unsigned pf[8][4];
#pragma unroll
        for (int nt = 0; nt < 8; nt++) {
            float p0 = __expf(sv[nt][0] - mn0);
            float p1 = __expf(sv[nt][1] - mn0);
            float p2 = __expf(sv[nt][2] - mn1);
            float p3 = __expf(sv[nt][3] - mn1);
            l0a += p0 + p1;
            l1a += p2 + p3;
            pf[nt][0] = f2tf(p0);
            pf[nt][1] = f2tf(p2);
            pf[nt][2] = f2tf(p1);
            pf[nt][3] = f2tf(p3);
        }
        l0 = l0 * a0 + l0a;
        l1 = l1 * a1 + l1a;

#pragma unroll
        for (int nt = 0; nt < 16; nt++) {
            o[nt][0] *= a0; o[nt][1] *= a0;
            o[nt][2] *= a1; o[nt][3] *= a1;
        }

        // ---- O += P @ V (tf32, permuted-k convention; unchanged) ----
#pragma unroll
        for (int s = 0; s < 8; s++) {
            const float* vrow = Vs + (8 * s + 2 * c) * 132 + g;
#pragma unroll
            for (int nt = 0; nt < 16; nt++) {
                unsigned bv[2] = {__float_as_uint(vrow[nt * 8]),
                                  __float_as_uint(vrow[nt * 8 + 132])};
                mma_tf32(o[nt], pf[s], bv);
            }
        }
        __syncthreads();
    }

    l0 += __shfl_xor_sync(0xffffffffu, l0, 1);
    l0 += __shfl_xor_sync(0xffffffffu, l0, 2);
    l1 += __shfl_xor_sync(0xffffffffu, l1, 1);
    l1 += __shfl_xor_sync(0xffffffffu, l1, 2);
    const float inv0 = 1.f / l0;
    const float inv1 = 1.f / l1;

    // epilogue: write ctx as k-permuted half (feeds fp16 out-projection)
    __half* c0h = ctxh + ((size_t)b * SEQ + rowg0) * HID + (size_t)h * HDIM;
    __half* c1h = ctxh + ((size_t)b * SEQ + rowg1) * HID + (size_t)h * HDIM;
#pragma unroll
    for (int nt = 0; nt < 16; nt++) {
        const int Ccol = nt * 8 + 2 * c;
        const int col = (Ccol & ~15) + kperm_even(Ccol & 15);
        *(__half2*)(c0h + col) = __floats2half2_rn(o[nt][0] * inv0, o[nt][1] * inv0);
        *(__half2*)(c1h + col) = __floats2half2_rn(o[nt][2] * inv1, o[nt][3] * inv1);
    }
}

// ===========================================================================
extern "C" void kernel_launch(void* const* d_in, const int* in_sizes, int n_in,
                              void* d_out, int out_size) {
    const float* x      = (const float*)d_in[0];
    const float* w_qkv  = (const float*)d_in[1];
    const float* b_qkv  = (const float*)d_in[2];
    const float* w_out  = (const float*)d_in[3];
    const float* b_out  = (const float*)d_in[4];
    float* out = (float*)d_out;

    float*  qkv;  cudaGetSymbolAddress((void**)&qkv,  g_qkv);
    __half* qkvh; cudaGetSymbolAddress((void**)&qkvh, g_qkvh);
    __half* xh;   cudaGetSymbolAddress((void**)&xh,   g_xh);
    __half* wqh;  cudaGetSymbolAddress((void**)&wqh,  g_wqh);
    __half* woh;  cudaGetSymbolAddress((void**)&woh,  g_woh);
    __half* cth;  cudaGetSymbolAddress((void**)&cth,  g_cth);

    cudaFuncSetAttribute(hgemm_kernel<true>,
                         cudaFuncAttributeMaxDynamicSharedMemorySize, HG_SMEM_BYTES);
    cudaFuncSetAttribute(hgemm_kernel<false>,
                         cudaFuncAttributeMaxDynamicSharedMemorySize, HG_SMEM_BYTES);
    cudaFuncSetAttribute(flash_attn_tc_kernel,
                         cudaFuncAttributeMaxDynamicSharedMemorySize, AT_SMEM_BYTES);

    // 0) preprocess
    {
        int n2 = MROWS * HID / 2;
        h16_perm_copy<<<n2 / 256, 256>>>((const float2*)x, (__half2*)xh, n2, HID / 2);
        h16_perm_transpose<<<dim3(K3 / 32, HID / 32), dim3(32, 8)>>>(w_qkv, wqh, HID, K3);
        h16_perm_transpose<<<dim3(HID / 32, HID / 32), dim3(32, 8)>>>(w_out, woh, HID, HID);
    }

    // 1) QKV projection: fp32(tf32) qkv + half k-permuted qkvh
    hgemm_kernel<true><<<dim3(K3 / 128, MROWS / 128), 256, HG_SMEM_BYTES>>>(
        xh, wqh, b_qkv, qkv, qkvh, K3, HID);

    // 2) causal flash attention: fp16 QK + tf32 PV
    flash_attn_tc_kernel<<<dim3(SEQ / 128, NHEAD, BATCH), 256, AT_SMEM_BYTES>>>(
        qkv, qkvh, cth);

    // 3) output projection (fp16 mma, fp32 out)
    hgemm_kernel<false><<<dim3(HID / 128, MROWS / 128), 256, HG_SMEM_BYTES>>>(
        cth, woh, b_out, out, nullptr, HID, HID);
}